// round 5
// baseline (speedup 1.0000x reference)
#include <cuda_runtime.h>
#include <math.h>

// ---------------- problem constants ----------------
#define DMODEL 1024
#define DINNER 2048
#define DSTATE 16
#define DTRANK 64
#define XDBC   96        // DTRANK + 2*DSTATE
#define NB     2
#define NT     4096
#define NTOK   (NB*NT)   // 8192
#define EPSRMS 1e-5f

// ---------------- scratch (static device globals; no runtime alloc) ----------------
__device__ float g_xn[(size_t)NTOK * DMODEL];          //  33.5 MB
__device__ float g_xr[(size_t)NTOK * 2 * DINNER];      // 134   MB  (u_raw | res)
__device__ float g_u [(size_t)NTOK * DINNER];          //  67   MB  (post conv+silu)
__device__ float g_xdbc[(size_t)NTOK * XDBC];          //   3.1 MB  (dt | B | C)
__device__ float g_delta[(size_t)NTOK * DINNER];       //  67   MB
__device__ float g_y [(size_t)NTOK * DINNER];          //  67   MB  (gated scan output)

// ---------------- rmsnorm: one block per token ----------------
__global__ __launch_bounds__(256) void rms_kernel(const float* __restrict__ x,
                                                  const float* __restrict__ w,
                                                  float* __restrict__ xn)
{
    int row = blockIdx.x;
    const float4* xin = (const float4*)(x + (size_t)row * DMODEL);
    float4 v = xin[threadIdx.x];                   // 256 threads * 4 = 1024
    float ss = v.x*v.x + v.y*v.y + v.z*v.z + v.w*v.w;
    #pragma unroll
    for (int o = 16; o; o >>= 1) ss += __shfl_xor_sync(0xffffffffu, ss, o);
    __shared__ float sred[8];
    if ((threadIdx.x & 31) == 0) sred[threadIdx.x >> 5] = ss;
    __syncthreads();
    if (threadIdx.x < 8) {
        float t = sred[threadIdx.x];
        #pragma unroll
        for (int o = 4; o; o >>= 1) t += __shfl_xor_sync(0xffu, t, o);
        if (threadIdx.x == 0) sred[0] = t;
    }
    __syncthreads();
    float scale = rsqrtf(sred[0] * (1.0f / DMODEL) + EPSRMS);
    float4 wv = ((const float4*)w)[threadIdx.x];
    float4 o;
    o.x = v.x * scale * wv.x;  o.y = v.y * scale * wv.y;
    o.z = v.z * scale * wv.z;  o.w = v.w * scale * wv.w;
    ((float4*)(xn + (size_t)row * DMODEL))[threadIdx.x] = o;
}

// ---------------- general 128x128x16 fp32 GEMM, 8x8 per thread ----------------
// C[M,N] = A[M,K(lda)] @ B[K,N]  (+ Rsd elementwise when RES)
template<bool RES>
__global__ __launch_bounds__(256) void gemm128(const float* __restrict__ A,
                                               const float* __restrict__ B,
                                               const float* __restrict__ Rsd,
                                               float* __restrict__ C,
                                               int K, int N, int lda)
{
    __shared__ __align__(16) float As[16][128];   // transposed: As[k][m]
    __shared__ __align__(16) float Bs[16][128];
    int col0 = blockIdx.x * 128;
    long row0 = (long)blockIdx.y * 128;
    int tid = threadIdx.x;
    int tx = tid & 15, ty = tid >> 4;             // thread tile: rows ty*8, cols tx*8

    int ar  = tid >> 2;                            // 0..63
    int ac4 = (tid & 3) << 2;                      // 0,4,8,12
    int br  = tid >> 5;                            // 0..7
    int bc4 = (tid & 31) << 2;
    const float* Aptr = A + (row0 + ar) * (long)lda + ac4;
    const float* Bptr = B + (long)br * N + col0 + bc4;

    float acc[8][8] = {};

    for (int k0 = 0; k0 < K; k0 += 16) {
        float4 a0 = *(const float4*)(Aptr);
        float4 a1 = *(const float4*)(Aptr + 64 * (long)lda);
        float4 b0 = *(const float4*)(Bptr);
        float4 b1 = *(const float4*)(Bptr + 8 * (long)N);
        __syncthreads();
        As[ac4+0][ar] = a0.x; As[ac4+1][ar] = a0.y; As[ac4+2][ar] = a0.z; As[ac4+3][ar] = a0.w;
        As[ac4+0][ar+64] = a1.x; As[ac4+1][ar+64] = a1.y; As[ac4+2][ar+64] = a1.z; As[ac4+3][ar+64] = a1.w;
        *(float4*)&Bs[br][bc4]   = b0;
        *(float4*)&Bs[br+8][bc4] = b1;
        __syncthreads();
        #pragma unroll
        for (int k = 0; k < 16; k++) {
            float a[8], bb[8];
            *(float4*)&a[0]  = *(const float4*)&As[k][ty*8];
            *(float4*)&a[4]  = *(const float4*)&As[k][ty*8+4];
            *(float4*)&bb[0] = *(const float4*)&Bs[k][tx*8];
            *(float4*)&bb[4] = *(const float4*)&Bs[k][tx*8+4];
            #pragma unroll
            for (int i = 0; i < 8; i++)
                #pragma unroll
                for (int j = 0; j < 8; j++)
                    acc[i][j] = fmaf(a[i], bb[j], acc[i][j]);
        }
        Aptr += 16;
        Bptr += 16 * (long)N;
    }

    #pragma unroll
    for (int i = 0; i < 8; i++) {
        long ci = (row0 + ty*8 + i) * (long)N + col0 + tx*8;
        float4 v0 = make_float4(acc[i][0], acc[i][1], acc[i][2], acc[i][3]);
        float4 v1 = make_float4(acc[i][4], acc[i][5], acc[i][6], acc[i][7]);
        if (RES) {
            float4 r0 = *(const float4*)(Rsd + ci);
            float4 r1 = *(const float4*)(Rsd + ci + 4);
            v0.x += r0.x; v0.y += r0.y; v0.z += r0.z; v0.w += r0.w;
            v1.x += r1.x; v1.y += r1.y; v1.z += r1.z; v1.w += r1.w;
        }
        *(float4*)(C + ci)     = v0;
        *(float4*)(C + ci + 4) = v1;
    }
}

// ---------------- depthwise causal conv (K=4) + bias + silu ----------------
__global__ __launch_bounds__(256) void conv_kernel(const float* __restrict__ xr,
                                                   const float* __restrict__ cw,
                                                   const float* __restrict__ cb,
                                                   float* __restrict__ u)
{
    int idx = blockIdx.x * 256 + threadIdx.x;     // < NTOK*DINNER
    int d   = idx & (DINNER - 1);
    int tok = idx >> 11;
    int t   = tok & (NT - 1);
    const float* p = xr + (size_t)tok * (2*DINNER) + d;   // u_raw is cols [0,2048)
    float w0 = cw[d*4+0], w1 = cw[d*4+1], w2 = cw[d*4+2], w3 = cw[d*4+3];
    float acc = cb[d] + w3 * p[0];
    if (t >= 1) acc = fmaf(w2, p[-(2*DINNER)],   acc);
    if (t >= 2) acc = fmaf(w1, p[-2*(2*DINNER)], acc);
    if (t >= 3) acc = fmaf(w0, p[-3*(2*DINNER)], acc);
    u[idx] = acc / (1.0f + __expf(-acc));         // silu
}

// ---------------- GEMM2: u[8192,2048] @ w_x[2048,96] -> xdbc[8192,96] ----------------
__global__ __launch_bounds__(256) void gemm_wx(const float* __restrict__ A,
                                               const float* __restrict__ W,
                                               float* __restrict__ C)
{
    __shared__ __align__(16) float As[16][64];    // transposed
    __shared__ float Ws[16][96];
    long row0 = (long)blockIdx.x * 64;
    int tid = threadIdx.x;
    int tx = tid & 15, ty = tid >> 4;             // rows ty*4, cols tx*6
    int ar  = tid >> 2;                            // 0..63
    int ac4 = (tid & 3) << 2;
    const float* Aptr = A + (row0 + ar) * (long)DINNER + ac4;

    float acc[4][6] = {};
    for (int k0 = 0; k0 < DINNER; k0 += 16) {
        float4 a0 = *(const float4*)(Aptr);
        __syncthreads();
        As[ac4+0][ar] = a0.x; As[ac4+1][ar] = a0.y; As[ac4+2][ar] = a0.z; As[ac4+3][ar] = a0.w;
        #pragma unroll
        for (int i = 0; i < 6; i++) {
            int idx = tid + i * 256;               // < 1536 = 16*96
            int r = idx / 96, c = idx - r * 96;
            Ws[r][c] = W[(k0 + r) * XDBC + c];
        }
        __syncthreads();
        #pragma unroll
        for (int k = 0; k < 16; k++) {
            float a[4];
            *(float4*)&a[0] = *(const float4*)&As[k][ty*4];
            float wv[6];
            #pragma unroll
            for (int j = 0; j < 6; j++) wv[j] = Ws[k][tx*6 + j];
            #pragma unroll
            for (int i = 0; i < 4; i++)
                #pragma unroll
                for (int j = 0; j < 6; j++)
                    acc[i][j] = fmaf(a[i], wv[j], acc[i][j]);
        }
        Aptr += 16;
    }
    #pragma unroll
    for (int i = 0; i < 4; i++)
        #pragma unroll
        for (int j = 0; j < 6; j++)
            C[(row0 + ty*4 + i) * (long)XDBC + tx*6 + j] = acc[i][j];
}

// ---------------- GEMM3: dt[8192,64(lda=96)] @ w_dt[64,2048] + b_dt -> softplus -> delta ----------------
__global__ __launch_bounds__(256) void gemm_dt(const float* __restrict__ A,
                                               const float* __restrict__ W,
                                               const float* __restrict__ bias,
                                               float* __restrict__ C)
{
    __shared__ __align__(16) float As[64][64];    // transposed: As[k][m]
    __shared__ __align__(16) float Bs[64][64];
    long row0 = (long)blockIdx.y * 64;
    int col0 = blockIdx.x * 64;
    int tid = threadIdx.x;

    #pragma unroll
    for (int i = 0; i < 4; i++) {                 // A tile 64x64, lda=96
        int idx = tid + i * 256;
        int r = idx >> 4, c4 = (idx & 15) << 2;
        float4 v = *(const float4*)(A + (row0 + r) * (long)XDBC + c4);
        As[c4+0][r] = v.x; As[c4+1][r] = v.y; As[c4+2][r] = v.z; As[c4+3][r] = v.w;
    }
    #pragma unroll
    for (int i = 0; i < 4; i++) {                 // B tile 64x64
        int idx = tid + i * 256;
        int r = idx >> 4, c4 = (idx & 15) << 2;
        *(float4*)&Bs[r][c4] = *(const float4*)(W + (long)r * DINNER + col0 + c4);
    }
    __syncthreads();

    int tx = tid & 15, ty = tid >> 4;             // rows ty*4, cols tx*4
    float acc[4][4] = {};
    #pragma unroll
    for (int k = 0; k < 64; k++) {
        float a[4], b[4];
        *(float4*)&a[0] = *(const float4*)&As[k][ty*4];
        *(float4*)&b[0] = *(const float4*)&Bs[k][tx*4];
        #pragma unroll
        for (int i = 0; i < 4; i++)
            #pragma unroll
            for (int j = 0; j < 4; j++)
                acc[i][j] = fmaf(a[i], b[j], acc[i][j]);
    }

    float4 bias4 = *(const float4*)(bias + col0 + tx*4);
    float bb[4] = {bias4.x, bias4.y, bias4.z, bias4.w};
    #pragma unroll
    for (int i = 0; i < 4; i++) {
        float4 o;
        float* op = &o.x;
        #pragma unroll
        for (int j = 0; j < 4; j++) {
            float v = acc[i][j] + bb[j];
            op[j] = (v > 20.0f) ? v : log1pf(expf(v));   // softplus
        }
        *(float4*)(C + (row0 + ty*4 + i) * (long)DINNER + col0 + tx*4) = o;
    }
}

// ---------------- selective scan ----------------
// warp -> 2 channels, lanes 0-15 / 16-31 -> 16 states each. h serial chain: EX2 + FMA.
// Operands staged in SMEM per 64-step chunk; y buffered + flushed coalesced with
// the fused epilogue  y = (scan + u*D) * silu(res).
__global__ __launch_bounds__(128) void scan_kernel(const float* __restrict__ delta,
                                                   const float* __restrict__ u,
                                                   const float* __restrict__ xdbc,
                                                   const float* __restrict__ xr,
                                                   const float* __restrict__ A_log,
                                                   const float* __restrict__ Dp,
                                                   float* __restrict__ y)
{
    __shared__ float sd[64][8], su[64][8], sres[64][8], ybuf[64][8];
    __shared__ float sbc[64][32];
    __shared__ float sD[8];

    int b     = blockIdx.x >> 8;                  // 512 blocks: 256 per batch
    int dbase = (blockIdx.x & 255) * 8;
    int tid   = threadIdx.x;
    int lane  = tid & 31, w = tid >> 5;
    int dloc  = 2 * w + (lane >> 4);
    int n     = lane & 15;
    int d     = dbase + dloc;

    float Ac = -expf(A_log[d * DSTATE + n]);      // A = -exp(A_log)
    if (tid < 8) sD[tid] = Dp[dbase + tid];

    float h = 0.0f;
    long tokbase = (long)b * NT;

    for (int c = 0; c < NT / 64; c++) {
        int t0 = c * 64;
        for (int i = tid; i < 512; i += 128) {    // 64 t x 8 d
            int tl = i >> 3, dl = i & 7;
            long g = (tokbase + t0 + tl) * (long)DINNER + dbase + dl;
            sd[tl][dl]   = delta[g];
            su[tl][dl]   = u[g];
            sres[tl][dl] = xr[(tokbase + t0 + tl) * (long)(2*DINNER) + DINNER + dbase + dl];
        }
        for (int i = tid; i < 2048; i += 128) {   // 64 t x 32 (B|C)
            int tl = i >> 5, cc = i & 31;
            sbc[tl][cc] = xdbc[(tokbase + t0 + tl) * (long)XDBC + DTRANK + cc];
        }
        __syncthreads();

        #pragma unroll 4
        for (int tl = 0; tl < 64; tl++) {
            float dlt = sd[tl][dloc];
            float uu  = su[tl][dloc];
            float a   = __expf(dlt * Ac);
            h = fmaf(a, h, dlt * uu * sbc[tl][n]);
            float p = h * sbc[tl][16 + n];
            p += __shfl_xor_sync(0xffffffffu, p, 8);
            p += __shfl_xor_sync(0xffffffffu, p, 4);
            p += __shfl_xor_sync(0xffffffffu, p, 2);
            p += __shfl_xor_sync(0xffffffffu, p, 1);
            if (n == 0) ybuf[tl][dloc] = p;
        }
        __syncthreads();

        for (int i = tid; i < 512; i += 128) {    // coalesced fused epilogue flush
            int tl = i >> 3, dl = i & 7;
            float uu = su[tl][dl];
            float r  = sres[tl][dl];
            float yy = (ybuf[tl][dl] + uu * sD[dl]) * (r / (1.0f + __expf(-r)));
            y[(tokbase + t0 + tl) * (long)DINNER + dbase + dl] = yy;
        }
        __syncthreads();
    }
}

// ---------------- launch ----------------
extern "C" void kernel_launch(void* const* d_in, const int* in_sizes, int n_in,
                              void* d_out, int out_size)
{
    (void)in_sizes; (void)n_in; (void)out_size;
    const float* x      = (const float*)d_in[0];
    const float* norm_w = (const float*)d_in[1];
    const float* w_in   = (const float*)d_in[2];
    const float* conv_w = (const float*)d_in[3];
    const float* conv_b = (const float*)d_in[4];
    const float* w_x    = (const float*)d_in[5];
    const float* w_dt   = (const float*)d_in[6];
    const float* b_dt   = (const float*)d_in[7];
    const float* A_log  = (const float*)d_in[8];
    const float* Dp     = (const float*)d_in[9];
    const float* w_out  = (const float*)d_in[10];
    float* out = (float*)d_out;

    float *p_xn, *p_xr, *p_u, *p_xdbc, *p_delta, *p_y;
    cudaGetSymbolAddress((void**)&p_xn,    g_xn);
    cudaGetSymbolAddress((void**)&p_xr,    g_xr);
    cudaGetSymbolAddress((void**)&p_u,     g_u);
    cudaGetSymbolAddress((void**)&p_xdbc,  g_xdbc);
    cudaGetSymbolAddress((void**)&p_delta, g_delta);
    cudaGetSymbolAddress((void**)&p_y,     g_y);

    // 1. rmsnorm
    rms_kernel<<<NTOK, 256>>>(x, norm_w, p_xn);
    // 2. xr = xn @ w_in   (8192 x 4096, K=1024)
    gemm128<false><<<dim3(4096/128, NTOK/128), 256>>>(p_xn, w_in, nullptr, p_xr, DMODEL, 2*DINNER, DMODEL);
    // 3. u = silu(depthwise_conv(xr[:, :2048]) + conv_b)
    conv_kernel<<<(NTOK*DINNER)/256, 256>>>(p_xr, conv_w, conv_b, p_u);
    // 4. xdbc = u @ w_x   (8192 x 96, K=2048)
    gemm_wx<<<NTOK/64, 256>>>(p_u, w_x, p_xdbc);
    // 5. delta = softplus(dt @ w_dt + b_dt)  (8192 x 2048, K=64)
    gemm_dt<<<dim3(DINNER/64, NTOK/64), 256>>>(p_xdbc, w_dt, b_dt, p_delta);
    // 6. selective scan + gating -> y
    scan_kernel<<<NB*256, 128>>>(p_delta, p_u, p_xdbc, p_xr, A_log, Dp, p_y);
    // 7. out = y @ w_out + x   (8192 x 1024, K=2048)
    gemm128<true><<<dim3(1024/128, NTOK/128), 256>>>(p_y, w_out, x, out, DINNER, DMODEL, DINNER);
}

// round 6
// speedup vs baseline: 2.0720x; 2.0720x over previous
#include <cuda_runtime.h>
#include <math.h>

// ---------------- problem constants ----------------
#define DMODEL 1024
#define DINNER 2048
#define DSTATE 16
#define DTRANK 64
#define XDBC   96        // DTRANK + 2*DSTATE
#define NB     2
#define NT     4096
#define NTOK   (NB*NT)   // 8192
#define EPSRMS 1e-5f

// ---------------- scratch (static device globals; no runtime alloc) ----------------
__device__ float g_xn[(size_t)NTOK * DMODEL];
__device__ float g_xr[(size_t)NTOK * 2 * DINNER];      // (u_raw | res)
__device__ float g_u [(size_t)NTOK * DINNER];
__device__ float g_xdbc[(size_t)NTOK * XDBC];          // (dt | B | C)
__device__ float g_delta[(size_t)NTOK * DINNER];
__device__ float g_y [(size_t)NTOK * DINNER];

// ---------------- rmsnorm: one block per token ----------------
__global__ __launch_bounds__(256) void rms_kernel(const float* __restrict__ x,
                                                  const float* __restrict__ w,
                                                  float* __restrict__ xn)
{
    int row = blockIdx.x;
    const float4* xin = (const float4*)(x + (size_t)row * DMODEL);
    float4 v = xin[threadIdx.x];
    float ss = v.x*v.x + v.y*v.y + v.z*v.z + v.w*v.w;
    #pragma unroll
    for (int o = 16; o; o >>= 1) ss += __shfl_xor_sync(0xffffffffu, ss, o);
    __shared__ float sred[8];
    if ((threadIdx.x & 31) == 0) sred[threadIdx.x >> 5] = ss;
    __syncthreads();
    if (threadIdx.x < 8) {
        float t = sred[threadIdx.x];
        #pragma unroll
        for (int o = 4; o; o >>= 1) t += __shfl_xor_sync(0xffu, t, o);
        if (threadIdx.x == 0) sred[0] = t;
    }
    __syncthreads();
    float scale = rsqrtf(sred[0] * (1.0f / DMODEL) + EPSRMS);
    float4 wv = ((const float4*)w)[threadIdx.x];
    float4 o;
    o.x = v.x * scale * wv.x;  o.y = v.y * scale * wv.y;
    o.z = v.z * scale * wv.z;  o.w = v.w * scale * wv.w;
    ((float4*)(xn + (size_t)row * DMODEL))[threadIdx.x] = o;
}

// ---------------- tf32 tensor-core GEMM ----------------
// C[M,N] = A[M,K(lda)] @ B[K,N]  (+ Rsd when RES)
// 128x128x16 block tile, 128 threads = 4 warps, warp tile 64x64 (4x8 mma m16n8k8).
// A staged transposed As[k][m] with XOR swizzle m ^= ((k>>2)&3)<<3 so that both
// the transpose STS and the fragment LDS are bank-conflict-free (stride 136 => 8 mod 32).

__device__ __forceinline__ float to_tf32(float x) {
    float r;
    asm("cvt.rna.tf32.f32 %0, %1;" : "=f"(r) : "f"(x));
    return r;
}

__device__ __forceinline__ void mma_tf32(float* c, const float* a, const float* b) {
    asm volatile(
        "mma.sync.aligned.m16n8k8.row.col.f32.tf32.tf32.f32 "
        "{%0,%1,%2,%3}, {%4,%5,%6,%7}, {%8,%9}, {%0,%1,%2,%3};\n"
        : "+f"(c[0]), "+f"(c[1]), "+f"(c[2]), "+f"(c[3])
        : "r"(__float_as_uint(a[0])), "r"(__float_as_uint(a[1])),
          "r"(__float_as_uint(a[2])), "r"(__float_as_uint(a[3])),
          "r"(__float_as_uint(b[0])), "r"(__float_as_uint(b[1])));
}

template<bool RES>
__global__ __launch_bounds__(128) void gemm_tc(const float* __restrict__ A,
                                               const float* __restrict__ B,
                                               const float* __restrict__ Rsd,
                                               float* __restrict__ C,
                                               int K, int N, int lda)
{
    __shared__ float As[16][136];
    __shared__ float Bs[16][136];
    int tid = threadIdx.x;
    int col0 = blockIdx.x * 128;
    long row0 = (long)blockIdx.y * 128;

    int lane = tid & 31, warp = tid >> 5;
    int wm = warp >> 1, wn = warp & 1;
    int gid = lane >> 2, tg = lane & 3;
    int mW = wm * 64, nW = wn * 64;

    // gmem staging mapping
    int arow = tid >> 2;                 // 0..31
    int acg  = tid & 3;                  // 0..3 (k-group of 4)
    const float* Ap = A + (row0 + arow) * (long)lda + acg * 4;
    int bk  = tid >> 5;                  // 0..3
    int bn4 = tid & 31;
    const float* Bp = B + (long)bk * N + col0 + bn4 * 4;

    float4 pa[4], pb[4];
    #pragma unroll
    for (int i = 0; i < 4; i++) {
        pa[i] = *(const float4*)(Ap + (long)i * 32 * lda);
        pb[i] = *(const float4*)(Bp + (long)i * 4 * N);
    }

    float acc[4][8][4];
    #pragma unroll
    for (int mi = 0; mi < 4; mi++)
        #pragma unroll
        for (int ni = 0; ni < 8; ni++)
            #pragma unroll
            for (int j = 0; j < 4; j++) acc[mi][ni][j] = 0.f;

    int KT = K >> 4;
    for (int kt = 0; kt < KT; kt++) {
        __syncthreads();
        #pragma unroll
        for (int i = 0; i < 4; i++) {
            int r = arow + i * 32;
            float v[4] = {pa[i].x, pa[i].y, pa[i].z, pa[i].w};
            #pragma unroll
            for (int j = 0; j < 4; j++) {
                int c = acg * 4 + j;
                As[c][r ^ (((c >> 2) & 3) << 3)] = to_tf32(v[j]);
            }
            float4 q = pb[i];
            q.x = to_tf32(q.x); q.y = to_tf32(q.y);
            q.z = to_tf32(q.z); q.w = to_tf32(q.w);
            *(float4*)&Bs[bk + i * 4][bn4 * 4] = q;
        }
        __syncthreads();
        if (kt + 1 < KT) {
            #pragma unroll
            for (int i = 0; i < 4; i++) {
                pa[i] = *(const float4*)(Ap + (kt + 1) * 16 + (long)i * 32 * lda);
                pb[i] = *(const float4*)(Bp + (long)((kt + 1) * 16 + i * 4) * N);
            }
        }
        #pragma unroll
        for (int ks = 0; ks < 2; ks++) {
            int k0 = ks * 8;
            int kA = k0 + tg, kB = k0 + tg + 4;
            int sA = ((kA >> 2) & 3) << 3;
            int sB = ((kB >> 2) & 3) << 3;
            float a[4][4], b[8][2];
            #pragma unroll
            for (int mi = 0; mi < 4; mi++) {
                int m = mW + mi * 16 + gid;
                a[mi][0] = As[kA][m ^ sA];
                a[mi][1] = As[kA][(m + 8) ^ sA];
                a[mi][2] = As[kB][m ^ sB];
                a[mi][3] = As[kB][(m + 8) ^ sB];
            }
            #pragma unroll
            for (int ni = 0; ni < 8; ni++) {
                int n = nW + ni * 8 + gid;
                b[ni][0] = Bs[kA][n];
                b[ni][1] = Bs[kB][n];
            }
            #pragma unroll
            for (int mi = 0; mi < 4; mi++)
                #pragma unroll
                for (int ni = 0; ni < 8; ni++)
                    mma_tf32(acc[mi][ni], a[mi], b[ni]);
        }
    }

    // epilogue: c0,c1 -> (row, 2tg..2tg+1), c2,c3 -> (row+8, same cols)
    #pragma unroll
    for (int mi = 0; mi < 4; mi++) {
        long r = row0 + mW + mi * 16 + gid;
        #pragma unroll
        for (int ni = 0; ni < 8; ni++) {
            long c = col0 + nW + ni * 8 + 2 * tg;
            float2 v0 = make_float2(acc[mi][ni][0], acc[mi][ni][1]);
            float2 v1 = make_float2(acc[mi][ni][2], acc[mi][ni][3]);
            if (RES) {
                float2 r0 = *(const float2*)(Rsd + r * N + c);
                float2 r1 = *(const float2*)(Rsd + (r + 8) * N + c);
                v0.x += r0.x; v0.y += r0.y; v1.x += r1.x; v1.y += r1.y;
            }
            *(float2*)(C + r * N + c)       = v0;
            *(float2*)(C + (r + 8) * N + c) = v1;
        }
    }
}

// ---------------- depthwise causal conv (K=4) + bias + silu ----------------
__global__ __launch_bounds__(256) void conv_kernel(const float* __restrict__ xr,
                                                   const float* __restrict__ cw,
                                                   const float* __restrict__ cb,
                                                   float* __restrict__ u)
{
    int idx = blockIdx.x * 256 + threadIdx.x;
    int d   = idx & (DINNER - 1);
    int tok = idx >> 11;
    int t   = tok & (NT - 1);
    const float* p = xr + (size_t)tok * (2*DINNER) + d;
    float w0 = cw[d*4+0], w1 = cw[d*4+1], w2 = cw[d*4+2], w3 = cw[d*4+3];
    float acc = cb[d] + w3 * p[0];
    if (t >= 1) acc = fmaf(w2, p[-(2*DINNER)],   acc);
    if (t >= 2) acc = fmaf(w1, p[-2*(2*DINNER)], acc);
    if (t >= 3) acc = fmaf(w0, p[-3*(2*DINNER)], acc);
    u[idx] = acc / (1.0f + __expf(-acc));
}

// ---------------- GEMM2: u[8192,2048] @ w_x[2048,96] -> xdbc[8192,96] ----------------
// 32-row tiles -> grid 256 (was 128, occ-bound at 12.4%)
__global__ __launch_bounds__(256) void gemm_wx(const float* __restrict__ A,
                                               const float* __restrict__ W,
                                               float* __restrict__ C)
{
    __shared__ float As[16][34];          // transposed, padded (even stride for float2)
    __shared__ float Ws[16][96];
    long row0 = (long)blockIdx.x * 32;
    int tid = threadIdx.x;
    int tx = tid & 15, ty = tid >> 4;     // ty: 2 rows each
    int arow = tid >> 2, acg = tid & 3;   // valid for tid < 128
    const float* Ap = A + (row0 + arow) * (long)DINNER + acg * 4;

    float acc[2][6] = {};
    for (int k0 = 0; k0 < DINNER; k0 += 16) {
        float4 a0 = make_float4(0.f,0.f,0.f,0.f);
        if (tid < 128) a0 = *(const float4*)(Ap + k0);
        __syncthreads();
        if (tid < 128) {
            As[acg*4+0][arow] = a0.x; As[acg*4+1][arow] = a0.y;
            As[acg*4+2][arow] = a0.z; As[acg*4+3][arow] = a0.w;
        }
        #pragma unroll
        for (int i = 0; i < 6; i++) {
            int idx = tid + i * 256;      // < 1536 = 16*96
            int rr = idx / 96, cc = idx - rr * 96;
            Ws[rr][cc] = W[(k0 + rr) * XDBC + cc];
        }
        __syncthreads();
        #pragma unroll
        for (int k = 0; k < 16; k++) {
            float2 a = *(const float2*)&As[k][ty*2];
            #pragma unroll
            for (int j = 0; j < 6; j++) {
                float wv = Ws[k][tx*6+j];
                acc[0][j] = fmaf(a.x, wv, acc[0][j]);
                acc[1][j] = fmaf(a.y, wv, acc[1][j]);
            }
        }
    }
    #pragma unroll
    for (int i = 0; i < 2; i++)
        #pragma unroll
        for (int j = 0; j < 6; j++)
            C[(row0 + ty*2 + i) * (long)XDBC + tx*6 + j] = acc[i][j];
}

// ---------------- GEMM3: dt[8192,64(lda=96)] @ w_dt[64,2048] + b_dt -> softplus ----------------
__global__ __launch_bounds__(256) void gemm_dt(const float* __restrict__ A,
                                               const float* __restrict__ W,
                                               const float* __restrict__ bias,
                                               float* __restrict__ C)
{
    __shared__ __align__(16) float As[64][64];
    __shared__ __align__(16) float Bs[64][64];
    long row0 = (long)blockIdx.y * 64;
    int col0 = blockIdx.x * 64;
    int tid = threadIdx.x;

    #pragma unroll
    for (int i = 0; i < 4; i++) {
        int idx = tid + i * 256;
        int r = idx >> 4, c4 = (idx & 15) << 2;
        float4 v = *(const float4*)(A + (row0 + r) * (long)XDBC + c4);
        As[c4+0][r] = v.x; As[c4+1][r] = v.y; As[c4+2][r] = v.z; As[c4+3][r] = v.w;
    }
    #pragma unroll
    for (int i = 0; i < 4; i++) {
        int idx = tid + i * 256;
        int r = idx >> 4, c4 = (idx & 15) << 2;
        *(float4*)&Bs[r][c4] = *(const float4*)(W + (long)r * DINNER + col0 + c4);
    }
    __syncthreads();

    int tx = tid & 15, ty = tid >> 4;
    float acc[4][4] = {};
    #pragma unroll
    for (int k = 0; k < 64; k++) {
        float a[4], b[4];
        *(float4*)&a[0] = *(const float4*)&As[k][ty*4];
        *(float4*)&b[0] = *(const float4*)&Bs[k][tx*4];
        #pragma unroll
        for (int i = 0; i < 4; i++)
            #pragma unroll
            for (int j = 0; j < 4; j++)
                acc[i][j] = fmaf(a[i], b[j], acc[i][j]);
    }

    float4 bias4 = *(const float4*)(bias + col0 + tx*4);
    float bb[4] = {bias4.x, bias4.y, bias4.z, bias4.w};
    #pragma unroll
    for (int i = 0; i < 4; i++) {
        float4 o;
        float* op = &o.x;
        #pragma unroll
        for (int j = 0; j < 4; j++) {
            float v = acc[i][j] + bb[j];
            op[j] = (v > 20.0f) ? v : log1pf(expf(v));
        }
        *(float4*)(C + (row0 + ty*4 + i) * (long)DINNER + col0 + tx*4) = o;
    }
}

// ---------------- selective scan ----------------
__global__ __launch_bounds__(128) void scan_kernel(const float* __restrict__ delta,
                                                   const float* __restrict__ u,
                                                   const float* __restrict__ xdbc,
                                                   const float* __restrict__ xr,
                                                   const float* __restrict__ A_log,
                                                   const float* __restrict__ Dp,
                                                   float* __restrict__ y)
{
    __shared__ float sd[64][8], su[64][8], sres[64][8], ybuf[64][8];
    __shared__ float sbc[64][32];
    __shared__ float sD[8];

    int b     = blockIdx.x >> 8;
    int dbase = (blockIdx.x & 255) * 8;
    int tid   = threadIdx.x;
    int lane  = tid & 31, w = tid >> 5;
    int dloc  = 2 * w + (lane >> 4);
    int n     = lane & 15;
    int d     = dbase + dloc;

    float Ac = -expf(A_log[d * DSTATE + n]);
    if (tid < 8) sD[tid] = Dp[dbase + tid];

    float h = 0.0f;
    long tokbase = (long)b * NT;

    for (int c = 0; c < NT / 64; c++) {
        int t0 = c * 64;
        for (int i = tid; i < 512; i += 128) {
            int tl = i >> 3, dl = i & 7;
            long g = (tokbase + t0 + tl) * (long)DINNER + dbase + dl;
            sd[tl][dl]   = delta[g];
            su[tl][dl]   = u[g];
            sres[tl][dl] = xr[(tokbase + t0 + tl) * (long)(2*DINNER) + DINNER + dbase + dl];
        }
        for (int i = tid; i < 2048; i += 128) {
            int tl = i >> 5, cc = i & 31;
            sbc[tl][cc] = xdbc[(tokbase + t0 + tl) * (long)XDBC + DTRANK + cc];
        }
        __syncthreads();

        #pragma unroll 4
        for (int tl = 0; tl < 64; tl++) {
            float dlt = sd[tl][dloc];
            float uu  = su[tl][dloc];
            float a   = __expf(dlt * Ac);
            h = fmaf(a, h, dlt * uu * sbc[tl][n]);
            float p = h * sbc[tl][16 + n];
            p += __shfl_xor_sync(0xffffffffu, p, 8);
            p += __shfl_xor_sync(0xffffffffu, p, 4);
            p += __shfl_xor_sync(0xffffffffu, p, 2);
            p += __shfl_xor_sync(0xffffffffu, p, 1);
            if (n == 0) ybuf[tl][dloc] = p;
        }
        __syncthreads();

        for (int i = tid; i < 512; i += 128) {
            int tl = i >> 3, dl = i & 7;
            float uu = su[tl][dl];
            float r  = sres[tl][dl];
            float yy = (ybuf[tl][dl] + uu * sD[dl]) * (r / (1.0f + __expf(-r)));
            y[(tokbase + t0 + tl) * (long)DINNER + dbase + dl] = yy;
        }
        __syncthreads();
    }
}

// ---------------- launch ----------------
extern "C" void kernel_launch(void* const* d_in, const int* in_sizes, int n_in,
                              void* d_out, int out_size)
{
    (void)in_sizes; (void)n_in; (void)out_size;
    const float* x      = (const float*)d_in[0];
    const float* norm_w = (const float*)d_in[1];
    const float* w_in   = (const float*)d_in[2];
    const float* conv_w = (const float*)d_in[3];
    const float* conv_b = (const float*)d_in[4];
    const float* w_x    = (const float*)d_in[5];
    const float* w_dt   = (const float*)d_in[6];
    const float* b_dt   = (const float*)d_in[7];
    const float* A_log  = (const float*)d_in[8];
    const float* Dp     = (const float*)d_in[9];
    const float* w_out  = (const float*)d_in[10];
    float* out = (float*)d_out;

    float *p_xn, *p_xr, *p_u, *p_xdbc, *p_delta, *p_y;
    cudaGetSymbolAddress((void**)&p_xn,    g_xn);
    cudaGetSymbolAddress((void**)&p_xr,    g_xr);
    cudaGetSymbolAddress((void**)&p_u,     g_u);
    cudaGetSymbolAddress((void**)&p_xdbc,  g_xdbc);
    cudaGetSymbolAddress((void**)&p_delta, g_delta);
    cudaGetSymbolAddress((void**)&p_y,     g_y);

    // 1. rmsnorm
    rms_kernel<<<NTOK, 256>>>(x, norm_w, p_xn);
    // 2. xr = xn @ w_in   (8192 x 4096, K=1024)  [tf32 mma]
    gemm_tc<false><<<dim3(4096/128, NTOK/128), 128>>>(p_xn, w_in, nullptr, p_xr, DMODEL, 2*DINNER, DMODEL);
    // 3. u = silu(depthwise_conv(xr[:, :2048]) + conv_b)
    conv_kernel<<<(NTOK*DINNER)/256, 256>>>(p_xr, conv_w, conv_b, p_u);
    // 4. xdbc = u @ w_x   (8192 x 96, K=2048)
    gemm_wx<<<NTOK/32, 256>>>(p_u, w_x, p_xdbc);
    // 5. delta = softplus(dt @ w_dt + b_dt)  (8192 x 2048, K=64)
    gemm_dt<<<dim3(DINNER/64, NTOK/64), 256>>>(p_xdbc, w_dt, b_dt, p_delta);
    // 6. selective scan + gating -> y
    scan_kernel<<<NB*256, 128>>>(p_delta, p_u, p_xdbc, p_xr, A_log, Dp, p_y);
    // 7. out = y @ w_out + x   (8192 x 1024, K=2048)  [tf32 mma]
    gemm_tc<true><<<dim3(1024/128, NTOK/128), 128>>>(p_y, w_out, x, out, DINNER, DMODEL, DINNER);
}

// round 7
// speedup vs baseline: 2.1596x; 1.0423x over previous
#include <cuda_runtime.h>
#include <math.h>

// ---------------- problem constants ----------------
#define DMODEL 1024
#define DINNER 2048
#define DSTATE 16
#define DTRANK 64
#define XDBC   96        // DTRANK + 2*DSTATE
#define NB     2
#define NT     4096
#define NTOK   (NB*NT)   // 8192
#define EPSRMS 1e-5f
#define WX_SPLIT 8

// ---------------- scratch (static device globals; no runtime alloc) ----------------
__device__ float g_xn[(size_t)NTOK * DMODEL];
__device__ float g_xr[(size_t)NTOK * 2 * DINNER];      // (u_raw | res)
__device__ float g_u [(size_t)NTOK * DINNER];
__device__ float g_xdbc[(size_t)NTOK * XDBC];          // (dt | B | C)
__device__ float g_delta[(size_t)NTOK * DINNER];
__device__ float g_y [(size_t)NTOK * DINNER];
__device__ float g_part[(size_t)WX_SPLIT * NTOK * XDBC];  // split-K partials for wx

// ---------------- helpers ----------------
__device__ __forceinline__ float to_tf32(float x) {
    float r;
    asm("cvt.rna.tf32.f32 %0, %1;" : "=f"(r) : "f"(x));
    return r;
}

__device__ __forceinline__ void mma_tf32(float* c, const float* a, const float* b) {
    asm volatile(
        "mma.sync.aligned.m16n8k8.row.col.f32.tf32.tf32.f32 "
        "{%0,%1,%2,%3}, {%4,%5,%6,%7}, {%8,%9}, {%0,%1,%2,%3};\n"
        : "+f"(c[0]), "+f"(c[1]), "+f"(c[2]), "+f"(c[3])
        : "r"(__float_as_uint(a[0])), "r"(__float_as_uint(a[1])),
          "r"(__float_as_uint(a[2])), "r"(__float_as_uint(a[3])),
          "r"(__float_as_uint(b[0])), "r"(__float_as_uint(b[1])));
}

__device__ __forceinline__ float softplusf(float v) {
    return (v > 20.0f) ? v : log1pf(expf(v));
}

// ---------------- rmsnorm: one block per token ----------------
__global__ __launch_bounds__(256) void rms_kernel(const float* __restrict__ x,
                                                  const float* __restrict__ w,
                                                  float* __restrict__ xn)
{
    int row = blockIdx.x;
    const float4* xin = (const float4*)(x + (size_t)row * DMODEL);
    float4 v = xin[threadIdx.x];
    float ss = v.x*v.x + v.y*v.y + v.z*v.z + v.w*v.w;
    #pragma unroll
    for (int o = 16; o; o >>= 1) ss += __shfl_xor_sync(0xffffffffu, ss, o);
    __shared__ float sred[8];
    if ((threadIdx.x & 31) == 0) sred[threadIdx.x >> 5] = ss;
    __syncthreads();
    if (threadIdx.x < 8) {
        float t = sred[threadIdx.x];
        #pragma unroll
        for (int o = 4; o; o >>= 1) t += __shfl_xor_sync(0xffu, t, o);
        if (threadIdx.x == 0) sred[0] = t;
    }
    __syncthreads();
    float scale = rsqrtf(sred[0] * (1.0f / DMODEL) + EPSRMS);
    float4 wv = ((const float4*)w)[threadIdx.x];
    float4 o;
    o.x = v.x * scale * wv.x;  o.y = v.y * scale * wv.y;
    o.z = v.z * scale * wv.z;  o.w = v.w * scale * wv.w;
    ((float4*)(xn + (size_t)row * DMODEL))[threadIdx.x] = o;
}

// ---------------- tf32 tensor-core GEMM v2 ----------------
// C[M,N] = A[M,K(lda)] @ B[K,N]  (+ epilogue)
// 128x128 block tile, 256 threads / 8 warps (warp tile 32x64), double-buffered
// smem (one __syncthreads per k-tile), register prefetch overlapping compute.
// EPI: 0 = none, 1 = +Aux[r,c] residual, 2 = softplus(acc + Aux[c]) bias.
template<int EPI>
__global__ __launch_bounds__(256) void gemm_tc(const float* __restrict__ A,
                                               const float* __restrict__ B,
                                               const float* __restrict__ Aux,
                                               float* __restrict__ C,
                                               int K, int N, int lda)
{
    __shared__ float As[2][16][136];
    __shared__ float Bs[2][16][136];
    const int tid = threadIdx.x;
    const int col0 = blockIdx.x * 128;
    const long row0 = (long)blockIdx.y * 128;
    const int lane = tid & 31, warp = tid >> 5;
    const int mW = (warp >> 1) * 32, nW = (warp & 1) * 64;
    const int gid = lane >> 2, tg = lane & 3;

    // gmem staging mapping
    const int arow = tid >> 2;           // 0..63 (rows arow, arow+64)
    const int acg  = tid & 3;
    const float* Ap = A + (row0 + arow) * (long)lda + acg * 4;
    const int bk  = tid >> 5;            // 0..7 (rows bk, bk+8)
    const int bn4 = tid & 31;
    const float* Bp = B + (long)bk * N + col0 + bn4 * 4;

    float4 pa[2], pb[2];
    pa[0] = *(const float4*)(Ap);
    pa[1] = *(const float4*)(Ap + 64 * (long)lda);
    pb[0] = *(const float4*)(Bp);
    pb[1] = *(const float4*)(Bp + 8 * (long)N);

    float acc[2][8][4];
    #pragma unroll
    for (int mi = 0; mi < 2; mi++)
        #pragma unroll
        for (int ni = 0; ni < 8; ni++)
            #pragma unroll
            for (int j = 0; j < 4; j++) acc[mi][ni][j] = 0.f;

    const int KT = K >> 4;
    int buf = 0;
    // initial smem fill (stage 0)
    #pragma unroll
    for (int i = 0; i < 2; i++) {
        int r = arow + i * 64;
        float v[4] = {pa[i].x, pa[i].y, pa[i].z, pa[i].w};
        #pragma unroll
        for (int j = 0; j < 4; j++) {
            int c = acg * 4 + j;
            As[0][c][r ^ (((c >> 2) & 3) << 3)] = to_tf32(v[j]);
        }
        float4 q = pb[i];
        q.x = to_tf32(q.x); q.y = to_tf32(q.y);
        q.z = to_tf32(q.z); q.w = to_tf32(q.w);
        *(float4*)&Bs[0][bk + i * 8][bn4 * 4] = q;
    }
    __syncthreads();

    for (int kt = 0; kt < KT; kt++) {
        if (kt + 1 < KT) {
            pa[0] = *(const float4*)(Ap + (kt + 1) * 16);
            pa[1] = *(const float4*)(Ap + (kt + 1) * 16 + 64 * (long)lda);
            pb[0] = *(const float4*)(Bp + (long)((kt + 1) * 16) * N);
            pb[1] = *(const float4*)(Bp + (long)((kt + 1) * 16 + 8) * N);
        }
        #pragma unroll
        for (int ks = 0; ks < 2; ks++) {
            const int k0 = ks * 8;
            const int kA = k0 + tg, kB = k0 + tg + 4;
            const int sA = ((kA >> 2) & 3) << 3;
            const int sB = ((kB >> 2) & 3) << 3;
            float a[2][4], b[8][2];
            #pragma unroll
            for (int mi = 0; mi < 2; mi++) {
                int m = mW + mi * 16 + gid;
                a[mi][0] = As[buf][kA][m ^ sA];
                a[mi][1] = As[buf][kA][(m + 8) ^ sA];
                a[mi][2] = As[buf][kB][m ^ sB];
                a[mi][3] = As[buf][kB][(m + 8) ^ sB];
            }
            #pragma unroll
            for (int ni = 0; ni < 8; ni++) {
                int n = nW + ni * 8 + gid;
                b[ni][0] = Bs[buf][kA][n];
                b[ni][1] = Bs[buf][kB][n];
            }
            #pragma unroll
            for (int mi = 0; mi < 2; mi++)
                #pragma unroll
                for (int ni = 0; ni < 8; ni++)
                    mma_tf32(acc[mi][ni], a[mi], b[ni]);
        }
        if (kt + 1 < KT) {
            int nb = buf ^ 1;
            #pragma unroll
            for (int i = 0; i < 2; i++) {
                int r = arow + i * 64;
                float v[4] = {pa[i].x, pa[i].y, pa[i].z, pa[i].w};
                #pragma unroll
                for (int j = 0; j < 4; j++) {
                    int c = acg * 4 + j;
                    As[nb][c][r ^ (((c >> 2) & 3) << 3)] = to_tf32(v[j]);
                }
                float4 q = pb[i];
                q.x = to_tf32(q.x); q.y = to_tf32(q.y);
                q.z = to_tf32(q.z); q.w = to_tf32(q.w);
                *(float4*)&Bs[nb][bk + i * 8][bn4 * 4] = q;
            }
            __syncthreads();
            buf = nb;
        }
    }

    // epilogue
    #pragma unroll
    for (int mi = 0; mi < 2; mi++) {
        long r = row0 + mW + mi * 16 + gid;
        #pragma unroll
        for (int ni = 0; ni < 8; ni++) {
            long c = col0 + nW + ni * 8 + 2 * tg;
            float2 v0 = make_float2(acc[mi][ni][0], acc[mi][ni][1]);
            float2 v1 = make_float2(acc[mi][ni][2], acc[mi][ni][3]);
            if (EPI == 1) {
                float2 r0 = *(const float2*)(Aux + r * N + c);
                float2 r1 = *(const float2*)(Aux + (r + 8) * N + c);
                v0.x += r0.x; v0.y += r0.y; v1.x += r1.x; v1.y += r1.y;
            }
            if (EPI == 2) {
                float b0 = Aux[c], b1 = Aux[c + 1];
                v0.x = softplusf(v0.x + b0); v0.y = softplusf(v0.y + b1);
                v1.x = softplusf(v1.x + b0); v1.y = softplusf(v1.y + b1);
            }
            *(float2*)(C + r * N + c)       = v0;
            *(float2*)(C + (r + 8) * N + c) = v1;
        }
    }
}

// ---------------- depthwise causal conv (K=4) + bias + silu ----------------
__global__ __launch_bounds__(256) void conv_kernel(const float* __restrict__ xr,
                                                   const float* __restrict__ cw,
                                                   const float* __restrict__ cb,
                                                   float* __restrict__ u)
{
    int idx = blockIdx.x * 256 + threadIdx.x;
    int d   = idx & (DINNER - 1);
    int tok = idx >> 11;
    int t   = tok & (NT - 1);
    const float* p = xr + (size_t)tok * (2*DINNER) + d;
    float w0 = cw[d*4+0], w1 = cw[d*4+1], w2 = cw[d*4+2], w3 = cw[d*4+3];
    float acc = cb[d] + w3 * p[0];
    if (t >= 1) acc = fmaf(w2, p[-(2*DINNER)],   acc);
    if (t >= 2) acc = fmaf(w1, p[-2*(2*DINNER)], acc);
    if (t >= 3) acc = fmaf(w0, p[-3*(2*DINNER)], acc);
    u[idx] = acc / (1.0f + __expf(-acc));
}

// ---------------- gemm_wx: tf32 split-K tensor GEMM ----------------
// u[8192,2048] @ w_x[2048,96] -> partials P[split][8192][96]
// grid: (M/128, WX_SPLIT), 128 threads / 4 warps (warp tile 64x48), K chunk 256.
__global__ __launch_bounds__(128) void gemm_wx_tc(const float* __restrict__ A,
                                                  const float* __restrict__ W,
                                                  float* __restrict__ P)
{
    __shared__ float As[2][16][136];
    __shared__ float Ws[2][16][104];
    const int tid = threadIdx.x;
    const long row0 = (long)blockIdx.x * 128;
    const int kblk = blockIdx.y;
    const int lane = tid & 31, warp = tid >> 5;
    const int mW = (warp >> 1) * 64, nW = (warp & 1) * 48;
    const int gid = lane >> 2, tg = lane & 3;

    const int arow = tid >> 2;           // 0..31 (rows arow + 32i)
    const int acg  = tid & 3;
    const float* Ap = A + (row0 + arow) * (long)DINNER + kblk * 256 + acg * 4;
    // W staging: 16x96 tile = 384 float4, 3 per thread
    int wr[3], wc[3];
    #pragma unroll
    for (int i = 0; i < 3; i++) {
        int idx = tid + i * 128;
        wr[i] = idx / 24; wc[i] = idx - wr[i] * 24;
    }
    const float* Wp = W + (long)(kblk * 256) * XDBC;

    float4 pa[4], pw[3];
    #pragma unroll
    for (int i = 0; i < 4; i++) pa[i] = *(const float4*)(Ap + (long)i * 32 * DINNER);
    #pragma unroll
    for (int i = 0; i < 3; i++) pw[i] = *(const float4*)(Wp + (long)wr[i] * XDBC + wc[i] * 4);

    float acc[4][6][4];
    #pragma unroll
    for (int mi = 0; mi < 4; mi++)
        #pragma unroll
        for (int ni = 0; ni < 6; ni++)
            #pragma unroll
            for (int j = 0; j < 4; j++) acc[mi][ni][j] = 0.f;

    int buf = 0;
    #pragma unroll
    for (int i = 0; i < 4; i++) {
        int r = arow + i * 32;
        float v[4] = {pa[i].x, pa[i].y, pa[i].z, pa[i].w};
        #pragma unroll
        for (int j = 0; j < 4; j++) {
            int c = acg * 4 + j;
            As[0][c][r ^ (((c >> 2) & 3) << 3)] = to_tf32(v[j]);
        }
    }
    #pragma unroll
    for (int i = 0; i < 3; i++) {
        float4 q = pw[i];
        q.x = to_tf32(q.x); q.y = to_tf32(q.y);
        q.z = to_tf32(q.z); q.w = to_tf32(q.w);
        *(float4*)&Ws[0][wr[i]][wc[i] * 4] = q;
    }
    __syncthreads();

    const int KT = 256 / 16;
    for (int kt = 0; kt < KT; kt++) {
        if (kt + 1 < KT) {
            #pragma unroll
            for (int i = 0; i < 4; i++)
                pa[i] = *(const float4*)(Ap + (kt + 1) * 16 + (long)i * 32 * DINNER);
            #pragma unroll
            for (int i = 0; i < 3; i++)
                pw[i] = *(const float4*)(Wp + (long)((kt + 1) * 16 + wr[i]) * XDBC + wc[i] * 4);
        }
        #pragma unroll
        for (int ks = 0; ks < 2; ks++) {
            const int k0 = ks * 8;
            const int kA = k0 + tg, kB = k0 + tg + 4;
            const int sA = ((kA >> 2) & 3) << 3;
            const int sB = ((kB >> 2) & 3) << 3;
            float a[4][4], b[6][2];
            #pragma unroll
            for (int mi = 0; mi < 4; mi++) {
                int m = mW + mi * 16 + gid;
                a[mi][0] = As[buf][kA][m ^ sA];
                a[mi][1] = As[buf][kA][(m + 8) ^ sA];
                a[mi][2] = As[buf][kB][m ^ sB];
                a[mi][3] = As[buf][kB][(m + 8) ^ sB];
            }
            #pragma unroll
            for (int ni = 0; ni < 6; ni++) {
                int n = nW + ni * 8 + gid;
                b[ni][0] = Ws[buf][kA][n];
                b[ni][1] = Ws[buf][kB][n];
            }
            #pragma unroll
            for (int mi = 0; mi < 4; mi++)
                #pragma unroll
                for (int ni = 0; ni < 6; ni++)
                    mma_tf32(acc[mi][ni], a[mi], b[ni]);
        }
        if (kt + 1 < KT) {
            int nb = buf ^ 1;
            #pragma unroll
            for (int i = 0; i < 4; i++) {
                int r = arow + i * 32;
                float v[4] = {pa[i].x, pa[i].y, pa[i].z, pa[i].w};
                #pragma unroll
                for (int j = 0; j < 4; j++) {
                    int c = acg * 4 + j;
                    As[nb][c][r ^ (((c >> 2) & 3) << 3)] = to_tf32(v[j]);
                }
            }
            #pragma unroll
            for (int i = 0; i < 3; i++) {
                float4 q = pw[i];
                q.x = to_tf32(q.x); q.y = to_tf32(q.y);
                q.z = to_tf32(q.z); q.w = to_tf32(q.w);
                *(float4*)&Ws[nb][wr[i]][wc[i] * 4] = q;
            }
            __syncthreads();
            buf = nb;
        }
    }

    float* Pb = P + (size_t)kblk * NTOK * XDBC;
    #pragma unroll
    for (int mi = 0; mi < 4; mi++) {
        long r = row0 + mW + mi * 16 + gid;
        #pragma unroll
        for (int ni = 0; ni < 6; ni++) {
            long c = nW + ni * 8 + 2 * tg;
            *(float2*)(Pb + r * XDBC + c)       = make_float2(acc[mi][ni][0], acc[mi][ni][1]);
            *(float2*)(Pb + (r + 8) * XDBC + c) = make_float2(acc[mi][ni][2], acc[mi][ni][3]);
        }
    }
}

__global__ __launch_bounds__(256) void wx_reduce(const float* __restrict__ P,
                                                 float* __restrict__ C)
{
    size_t i = (size_t)blockIdx.x * 256 + threadIdx.x;      // float4 index
    const float4* p = (const float4*)P;
    const size_t stride = (size_t)NTOK * XDBC / 4;
    float4 s = p[i];
    #pragma unroll
    for (int k = 1; k < WX_SPLIT; k++) {
        float4 t = p[i + (size_t)k * stride];
        s.x += t.x; s.y += t.y; s.z += t.z; s.w += t.w;
    }
    ((float4*)C)[i] = s;
}

// ---------------- selective scan ----------------
__global__ __launch_bounds__(128) void scan_kernel(const float* __restrict__ delta,
                                                   const float* __restrict__ u,
                                                   const float* __restrict__ xdbc,
                                                   const float* __restrict__ xr,
                                                   const float* __restrict__ A_log,
                                                   const float* __restrict__ Dp,
                                                   float* __restrict__ y)
{
    __shared__ float sd[64][8], su[64][8], sres[64][8], ybuf[64][8];
    __shared__ float sbc[64][32];
    __shared__ float sD[8];

    int b     = blockIdx.x >> 8;
    int dbase = (blockIdx.x & 255) * 8;
    int tid   = threadIdx.x;
    int lane  = tid & 31, w = tid >> 5;
    int dloc  = 2 * w + (lane >> 4);
    int n     = lane & 15;
    int d     = dbase + dloc;

    float Ac = -expf(A_log[d * DSTATE + n]);
    if (tid < 8) sD[tid] = Dp[dbase + tid];

    float h = 0.0f;
    long tokbase = (long)b * NT;

    for (int c = 0; c < NT / 64; c++) {
        int t0 = c * 64;
        for (int i = tid; i < 512; i += 128) {
            int tl = i >> 3, dl = i & 7;
            long g = (tokbase + t0 + tl) * (long)DINNER + dbase + dl;
            sd[tl][dl]   = delta[g];
            su[tl][dl]   = u[g];
            sres[tl][dl] = xr[(tokbase + t0 + tl) * (long)(2*DINNER) + DINNER + dbase + dl];
        }
        for (int i = tid; i < 2048; i += 128) {
            int tl = i >> 5, cc = i & 31;
            sbc[tl][cc] = xdbc[(tokbase + t0 + tl) * (long)XDBC + DTRANK + cc];
        }
        __syncthreads();

        #pragma unroll 4
        for (int tl = 0; tl < 64; tl++) {
            float dlt = sd[tl][dloc];
            float uu  = su[tl][dloc];
            float a   = __expf(dlt * Ac);
            h = fmaf(a, h, dlt * uu * sbc[tl][n]);
            float p = h * sbc[tl][16 + n];
            p += __shfl_xor_sync(0xffffffffu, p, 8);
            p += __shfl_xor_sync(0xffffffffu, p, 4);
            p += __shfl_xor_sync(0xffffffffu, p, 2);
            p += __shfl_xor_sync(0xffffffffu, p, 1);
            if (n == 0) ybuf[tl][dloc] = p;
        }
        __syncthreads();

        for (int i = tid; i < 512; i += 128) {
            int tl = i >> 3, dl = i & 7;
            float uu = su[tl][dl];
            float r  = sres[tl][dl];
            float yy = (ybuf[tl][dl] + uu * sD[dl]) * (r / (1.0f + __expf(-r)));
            y[(tokbase + t0 + tl) * (long)DINNER + dbase + dl] = yy;
        }
        __syncthreads();
    }
}

// ---------------- launch ----------------
extern "C" void kernel_launch(void* const* d_in, const int* in_sizes, int n_in,
                              void* d_out, int out_size)
{
    (void)in_sizes; (void)n_in; (void)out_size;
    const float* x      = (const float*)d_in[0];
    const float* norm_w = (const float*)d_in[1];
    const float* w_in   = (const float*)d_in[2];
    const float* conv_w = (const float*)d_in[3];
    const float* conv_b = (const float*)d_in[4];
    const float* w_x    = (const float*)d_in[5];
    const float* w_dt   = (const float*)d_in[6];
    const float* b_dt   = (const float*)d_in[7];
    const float* A_log  = (const float*)d_in[8];
    const float* Dp     = (const float*)d_in[9];
    const float* w_out  = (const float*)d_in[10];
    float* out = (float*)d_out;

    float *p_xn, *p_xr, *p_u, *p_xdbc, *p_delta, *p_y, *p_part;
    cudaGetSymbolAddress((void**)&p_xn,    g_xn);
    cudaGetSymbolAddress((void**)&p_xr,    g_xr);
    cudaGetSymbolAddress((void**)&p_u,     g_u);
    cudaGetSymbolAddress((void**)&p_xdbc,  g_xdbc);
    cudaGetSymbolAddress((void**)&p_delta, g_delta);
    cudaGetSymbolAddress((void**)&p_y,     g_y);
    cudaGetSymbolAddress((void**)&p_part,  g_part);

    // 1. rmsnorm
    rms_kernel<<<NTOK, 256>>>(x, norm_w, p_xn);
    // 2. xr = xn @ w_in   (8192 x 4096, K=1024)  [tf32 mma v2]
    gemm_tc<0><<<dim3(4096/128, NTOK/128), 256>>>(p_xn, w_in, nullptr, p_xr, DMODEL, 2*DINNER, DMODEL);
    // 3. u = silu(depthwise_conv(xr[:, :2048]) + conv_b)
    conv_kernel<<<(NTOK*DINNER)/256, 256>>>(p_xr, conv_w, conv_b, p_u);
    // 4. xdbc = u @ w_x   (8192 x 96, K=2048)  [tf32 split-K + reduce]
    gemm_wx_tc<<<dim3(NTOK/128, WX_SPLIT), 128>>>(p_u, w_x, p_part);
    wx_reduce<<<(NTOK*XDBC/4)/256, 256>>>(p_part, p_xdbc);
    // 5. delta = softplus(dt @ w_dt + b_dt)  (8192 x 2048, K=64)  [tf32 mma v2, bias+softplus epi]
    gemm_tc<2><<<dim3(DINNER/128, NTOK/128), 256>>>(p_xdbc, w_dt, b_dt, p_delta, DTRANK, DINNER, XDBC);
    // 6. selective scan + gating -> y
    scan_kernel<<<NB*256, 128>>>(p_delta, p_u, p_xdbc, p_xr, A_log, Dp, p_y);
    // 7. out = y @ w_out + x   (8192 x 1024, K=2048)  [tf32 mma v2, residual epi]
    gemm_tc<1><<<dim3(DMODEL/128, NTOK/128), 256>>>(p_y, w_out, x, out, DINNER, DMODEL, DINNER);
}